// round 5
// baseline (speedup 1.0000x reference)
#include <cuda_runtime.h>
#include <cuda_bf16.h>

// PatchShuffle: T=1024 (16 rows x 64 cols), B=64, C=768, STRIPE_W=48.
// perm per batch is closed-form (stable argsort of col + 64*in_stripe):
//   j < 16  -> (j < s ? j : j + 48)      [non-stripe cols ascending]
//   j >= 16 -> s + (j - 16)              [stripe cols ascending]
// inverse:
//   col < s        -> col
//   s <= col < s+48-> 16 + col - s
//   col >= s+48    -> col - 48
//
// d_out (float32) = [ visible (256*64*768) | fwd (1024*64) | bwd (1024*64) | stripe_bounds (2*64) ]

#define T_DIM   1024
#define B_DIM   64
#define C_DIM   768
#define C4      192          // C_DIM / 4
#define STRIPE  48
#define KEEP    16           // NUM_COLS - STRIPE_W
#define VIS_T   256          // NUM_ROWS * KEEP
#define VIS_ELEMS (VIS_T * B_DIM * C_DIM)        // 12,582,912 floats
#define FWD_ELEMS (T_DIM * B_DIM)                // 65,536
#define IDX_ELEMS (2 * FWD_ELEMS + 2 * B_DIM)    // 131,200
#define GATHER_THREADS4 (VIS_T * B_DIM * C4)     // 3,145,728 float4s

__device__ __forceinline__ int perm_col(int j, int s) {
    return (j < KEEP) ? (j < s ? j : j + STRIPE) : (s + j - KEEP);
}

// Streaming gather of the visible region: one thread = one float4.
// Writes are perfectly linear; reads are 3KB-contiguous per (t,b) row.
__global__ void __launch_bounds__(256) ps_gather_kernel(
    const float4* __restrict__ in,          // patches as float4
    const int*    __restrict__ start_cols,
    float4*       __restrict__ out)
{
    int idx = blockIdx.x * 256 + threadIdx.x;     // exact grid: no guard needed
    int c4  = idx % C4;
    int tb  = idx / C4;
    int b   = tb & 63;
    int t   = tb >> 6;
    int row = t >> 6;
    int j   = t & 63;
    int s   = __ldg(&start_cols[b]);
    int col = perm_col(j, s);
    int src = (row << 6) + col;                   // fwd[t][b]
    out[idx] = in[((src << 6) + b) * C4 + c4];
}

// fwd, bwd, stripe_bounds — all closed-form, written as floats.
__global__ void __launch_bounds__(256) ps_index_kernel(
    const int* __restrict__ start_cols,
    float*     __restrict__ out,
    long long  out_size)
{
    int idx = blockIdx.x * 256 + threadIdx.x;
    if (idx >= IDX_ELEMS) return;
    long long pos = (long long)VIS_ELEMS + idx;
    if (pos >= out_size) return;

    int val;
    if (idx < FWD_ELEMS) {
        // fwd[t][b] = row*64 + perm(j)
        int t = idx >> 6, b = idx & 63;
        int row = t >> 6, j = t & 63;
        int s = __ldg(&start_cols[b]);
        val = (row << 6) + perm_col(j, s);
    } else if (idx < 2 * FWD_ELEMS) {
        // bwd[i][b] = row*64 + invperm(col)
        int i2 = idx - FWD_ELEMS;
        int i = i2 >> 6, b = i2 & 63;
        int row = i >> 6, col = i & 63;
        int s = __ldg(&start_cols[b]);
        int j = (col < s) ? col
              : (col < s + STRIPE) ? (KEEP + col - s)
              : (col - STRIPE);
        val = (row << 6) + j;
    } else {
        // stripe_bounds[r][b] = s + r*STRIPE
        int i2 = idx - 2 * FWD_ELEMS;
        int r = i2 >> 6, b = i2 & 63;
        int s = __ldg(&start_cols[b]);
        val = s + r * STRIPE;
    }
    out[pos] = (float)val;
}

extern "C" void kernel_launch(void* const* d_in, const int* in_sizes, int n_in,
                              void* d_out, int out_size)
{
    const float* patches    = (const float*)d_in[0];
    const int*   start_cols = (const int*)d_in[1];
    float*       out        = (float*)d_out;

    if ((long long)out_size >= (long long)VIS_ELEMS) {
        ps_gather_kernel<<<GATHER_THREADS4 / 256, 256>>>(
            (const float4*)patches, start_cols, (float4*)out);
    }
    ps_index_kernel<<<(IDX_ELEMS + 255) / 256, 256>>>(
        start_cols, out, (long long)out_size);
}